// round 1
// baseline (speedup 1.0000x reference)
#include <cuda_runtime.h>
#include <cuda_bf16.h>
#include <stdint.h>

// Problem dims (fixed by the reference)
#define B_DIM  4096
#define N_IN   1024
#define N_HID  4096
#define N_OUT  1024

// Scratch for the hidden activations (allocation-free rule: __device__ global)
__device__ float g_h[(size_t)B_DIM * (size_t)N_HID];

// Tiling
#define BM 128
#define BN 128
#define BK 32
#define SPAD 8
#define SSTRIDE (BK + SPAD)   // 40 bf16 elements per row -> conflict-free frag loads

__device__ __forceinline__ void split2(float x0, float x1, uint32_t& hi, uint32_t& lo) {
    __nv_bfloat16 h0 = __float2bfloat16(x0);
    __nv_bfloat16 h1 = __float2bfloat16(x1);
    __nv_bfloat16 l0 = __float2bfloat16(x0 - __bfloat162float(h0));
    __nv_bfloat16 l1 = __float2bfloat16(x1 - __bfloat162float(h1));
    hi = (uint32_t)__bfloat16_as_ushort(h0) | ((uint32_t)__bfloat16_as_ushort(h1) << 16);
    lo = (uint32_t)__bfloat16_as_ushort(l0) | ((uint32_t)__bfloat16_as_ushort(l1) << 16);
}

__device__ __forceinline__ void mma_bf16(float* d, const uint32_t* a, const uint32_t* b) {
    asm volatile(
        "mma.sync.aligned.m16n8k16.row.col.f32.bf16.bf16.f32 "
        "{%0,%1,%2,%3}, {%4,%5,%6,%7}, {%8,%9}, {%0,%1,%2,%3};\n"
        : "+f"(d[0]), "+f"(d[1]), "+f"(d[2]), "+f"(d[3])
        : "r"(a[0]), "r"(a[1]), "r"(a[2]), "r"(a[3]), "r"(b[0]), "r"(b[1]));
}

// C[M,N] = act(A[M,K] @ Bw[K,N] + bias), fp32 in/out, bf16-split (hi/lo) tensor math.
template <bool RELU>
__global__ __launch_bounds__(256, 1)
void gemm_split_kernel(const float* __restrict__ A, const float* __restrict__ Bw,
                       const float* __restrict__ bias, float* __restrict__ C,
                       int M, int N, int K)
{
    __shared__ uint16_t As_hi[BM * SSTRIDE];
    __shared__ uint16_t As_lo[BM * SSTRIDE];
    __shared__ uint16_t Bs_hi[BN * SSTRIDE];
    __shared__ uint16_t Bs_lo[BN * SSTRIDE];

    const int tid  = threadIdx.x;
    const int lane = tid & 31;
    const int warp = tid >> 5;
    const int warp_m = (warp >> 1) * 32;   // 4 warps along M
    const int warp_n = (warp & 1) * 64;    // 2 warps along N

    const int row0 = blockIdx.y * BM;
    const int col0 = blockIdx.x * BN;

    float acc[2][8][4];
#pragma unroll
    for (int mt = 0; mt < 2; ++mt)
#pragma unroll
        for (int nt = 0; nt < 8; ++nt)
#pragma unroll
            for (int i = 0; i < 4; ++i) acc[mt][nt][i] = 0.f;

    for (int kt = 0; kt < K; kt += BK) {
        // ---- Load A tile (BM x BK fp32), convert to hi/lo bf16 in smem ----
        // 128x32 floats = 1024 float4; 256 threads x 4
#pragma unroll
        for (int i = 0; i < 4; ++i) {
            int idx = tid + i * 256;
            int r   = idx >> 3;          // row within tile (0..127)
            int c4  = (idx & 7) * 4;     // col within tile (0,4,..,28)
            float4 v = *reinterpret_cast<const float4*>(
                &A[(size_t)(row0 + r) * K + kt + c4]);
            uint32_t h01, l01, h23, l23;
            split2(v.x, v.y, h01, l01);
            split2(v.z, v.w, h23, l23);
            uint32_t off = r * SSTRIDE + c4;
            *reinterpret_cast<uint32_t*>(&As_hi[off])     = h01;
            *reinterpret_cast<uint32_t*>(&As_hi[off + 2]) = h23;
            *reinterpret_cast<uint32_t*>(&As_lo[off])     = l01;
            *reinterpret_cast<uint32_t*>(&As_lo[off + 2]) = l23;
        }
        // ---- Load B tile (BK x BN fp32), store transposed [n][k] hi/lo ----
#pragma unroll
        for (int i = 0; i < 4; ++i) {
            int idx = tid + i * 256;
            int r   = idx >> 5;          // k row within tile (0..31)
            int c4  = (idx & 31) * 4;    // n col within tile (0,4,..,124)
            float4 v = *reinterpret_cast<const float4*>(
                &Bw[(size_t)(kt + r) * N + col0 + c4]);
            float vv[4] = {v.x, v.y, v.z, v.w};
#pragma unroll
            for (int j = 0; j < 4; ++j) {
                __nv_bfloat16 h = __float2bfloat16(vv[j]);
                __nv_bfloat16 l = __float2bfloat16(vv[j] - __bfloat162float(h));
                uint32_t off = (uint32_t)(c4 + j) * SSTRIDE + r;
                Bs_hi[off] = __bfloat16_as_ushort(h);
                Bs_lo[off] = __bfloat16_as_ushort(l);
            }
        }
        __syncthreads();

        // ---- Compute: 2 k16-steps, 3 MMAs (hi*hi, hi*lo, lo*hi) per tile ----
#pragma unroll
        for (int ks = 0; ks < BK; ks += 16) {
            uint32_t ah[2][4], al[2][4];
#pragma unroll
            for (int mt = 0; mt < 2; ++mt) {
                int r = warp_m + mt * 16 + (lane >> 2);
                int c = ks + (lane & 3) * 2;
                uint32_t o = (uint32_t)r * SSTRIDE + c;
                ah[mt][0] = *reinterpret_cast<const uint32_t*>(&As_hi[o]);
                ah[mt][1] = *reinterpret_cast<const uint32_t*>(&As_hi[o + 8 * SSTRIDE]);
                ah[mt][2] = *reinterpret_cast<const uint32_t*>(&As_hi[o + 8]);
                ah[mt][3] = *reinterpret_cast<const uint32_t*>(&As_hi[o + 8 * SSTRIDE + 8]);
                al[mt][0] = *reinterpret_cast<const uint32_t*>(&As_lo[o]);
                al[mt][1] = *reinterpret_cast<const uint32_t*>(&As_lo[o + 8 * SSTRIDE]);
                al[mt][2] = *reinterpret_cast<const uint32_t*>(&As_lo[o + 8]);
                al[mt][3] = *reinterpret_cast<const uint32_t*>(&As_lo[o + 8 * SSTRIDE + 8]);
            }
            uint32_t bh[8][2], bl[8][2];
#pragma unroll
            for (int nt = 0; nt < 8; ++nt) {
                int n = warp_n + nt * 8 + (lane >> 2);
                int c = ks + (lane & 3) * 2;
                uint32_t o = (uint32_t)n * SSTRIDE + c;
                bh[nt][0] = *reinterpret_cast<const uint32_t*>(&Bs_hi[o]);
                bh[nt][1] = *reinterpret_cast<const uint32_t*>(&Bs_hi[o + 8]);
                bl[nt][0] = *reinterpret_cast<const uint32_t*>(&Bs_lo[o]);
                bl[nt][1] = *reinterpret_cast<const uint32_t*>(&Bs_lo[o + 8]);
            }
#pragma unroll
            for (int mt = 0; mt < 2; ++mt) {
#pragma unroll
                for (int nt = 0; nt < 8; ++nt) {
                    mma_bf16(acc[mt][nt], ah[mt], bh[nt]);   // hi*hi
                    mma_bf16(acc[mt][nt], ah[mt], bl[nt]);   // hi*lo
                    mma_bf16(acc[mt][nt], al[mt], bh[nt]);   // lo*hi
                }
            }
        }
        __syncthreads();
    }

    // ---- Epilogue: bias (+ReLU), fp32 stores ----
#pragma unroll
    for (int mt = 0; mt < 2; ++mt) {
#pragma unroll
        for (int nt = 0; nt < 8; ++nt) {
            int r = row0 + warp_m + mt * 16 + (lane >> 2);
            int c = col0 + warp_n + nt * 8 + (lane & 3) * 2;
            float bb0 = __ldg(&bias[c]);
            float bb1 = __ldg(&bias[c + 1]);
            float v0 = acc[mt][nt][0] + bb0;
            float v1 = acc[mt][nt][1] + bb1;
            float v2 = acc[mt][nt][2] + bb0;
            float v3 = acc[mt][nt][3] + bb1;
            if (RELU) {
                v0 = fmaxf(v0, 0.f); v1 = fmaxf(v1, 0.f);
                v2 = fmaxf(v2, 0.f); v3 = fmaxf(v3, 0.f);
            }
            *reinterpret_cast<float2*>(&C[(size_t)r * N + c]) = make_float2(v0, v1);
            *reinterpret_cast<float2*>(&C[(size_t)(r + 8) * N + c]) = make_float2(v2, v3);
        }
    }
}

extern "C" void kernel_launch(void* const* d_in, const int* in_sizes, int n_in,
                              void* d_out, int out_size) {
    const float* x  = (const float*)d_in[0];
    const float* W1 = (const float*)d_in[1];
    const float* b1 = (const float*)d_in[2];
    const float* W2 = (const float*)d_in[3];
    const float* b2 = (const float*)d_in[4];
    float* y = (float*)d_out;

    float* h = nullptr;
    cudaGetSymbolAddress((void**)&h, g_h);

    dim3 blk(256);
    dim3 g1(N_HID / BN, B_DIM / BM);   // 32 x 32 CTAs
    gemm_split_kernel<true><<<g1, blk>>>(x, W1, b1, h, B_DIM, N_HID, N_IN);

    dim3 g2(N_OUT / BN, B_DIM / BM);   // 8 x 32 CTAs
    gemm_split_kernel<false><<<g2, blk>>>(h, W2, b2, y, B_DIM, N_OUT, N_HID);
}

// round 3
// speedup vs baseline: 3.1303x; 3.1303x over previous
#include <cuda_runtime.h>
#include <cuda_bf16.h>
#include <stdint.h>

// ---------------- Problem dims ----------------
#define B_DIM  4096
#define N_IN   1024
#define N_HID  4096
#define N_OUT  1024

// ---------------- GEMM tiling ----------------
#define BM 128
#define BN 128
#define BK 64                 // bf16 elems per stage -> 128B rows (SW128 xor swizzle)
#define STAGES 3
#define OP_BYTES   (BM * 128)             // 16384 per operand-half per stage
#define STG_BYTES  (4 * OP_BYTES)         // Ah, Al, Bh, Bl = 65536
#define SMEM_TOTAL (STAGES * STG_BYTES)   // 196608

// ---------------- Device scratch (allocation-free rule) ----------------
__device__ __align__(128) __nv_bfloat16 g_xh [(size_t)B_DIM * N_IN];
__device__ __align__(128) __nv_bfloat16 g_xl [(size_t)B_DIM * N_IN];
__device__ __align__(128) __nv_bfloat16 g_w1h[(size_t)N_HID * N_IN];   // [N][K]
__device__ __align__(128) __nv_bfloat16 g_w1l[(size_t)N_HID * N_IN];
__device__ __align__(128) __nv_bfloat16 g_w2h[(size_t)N_OUT * N_HID];  // [N][K]
__device__ __align__(128) __nv_bfloat16 g_w2l[(size_t)N_OUT * N_HID];
__device__ __align__(128) __nv_bfloat16 g_hh [(size_t)B_DIM * N_HID];
__device__ __align__(128) __nv_bfloat16 g_hl [(size_t)B_DIM * N_HID];

// ---------------- PTX helpers ----------------
__device__ __forceinline__ uint32_t smem_u32(const void* p) {
    uint32_t a;
    asm("{ .reg .u64 t; cvta.to.shared.u64 t, %1; cvt.u32.u64 %0, t; }" : "=r"(a) : "l"(p));
    return a;
}
#define CP_ASYNC16(dst, src) \
    asm volatile("cp.async.cg.shared.global [%0], [%1], 16;" :: "r"(dst), "l"(src))
#define CP_COMMIT() asm volatile("cp.async.commit_group;" ::: "memory")
#define CP_WAIT2()  asm volatile("cp.async.wait_group 2;" ::: "memory")

#define LDSM4(r0, r1, r2, r3, a) \
    asm volatile("ldmatrix.sync.aligned.m8n8.x4.shared.b16 {%0,%1,%2,%3}, [%4];" \
                 : "=r"(r0), "=r"(r1), "=r"(r2), "=r"(r3) : "r"(a))

__device__ __forceinline__ void mma16816(float* d, const uint32_t* a, uint32_t b0, uint32_t b1) {
    asm volatile(
        "mma.sync.aligned.m16n8k16.row.col.f32.bf16.bf16.f32 "
        "{%0,%1,%2,%3}, {%4,%5,%6,%7}, {%8,%9}, {%0,%1,%2,%3};\n"
        : "+f"(d[0]), "+f"(d[1]), "+f"(d[2]), "+f"(d[3])
        : "r"(a[0]), "r"(a[1]), "r"(a[2]), "r"(a[3]), "r"(b0), "r"(b1));
}

__device__ __forceinline__ void split_bf16(float v, unsigned short& h, unsigned short& l) {
    __nv_bfloat16 hb = __float2bfloat16(v);
    __nv_bfloat16 lb = __float2bfloat16(v - __bfloat162float(hb));
    h = __bfloat16_as_ushort(hb);
    l = __bfloat16_as_ushort(lb);
}

// ---------------- Convert kernels ----------------

// Elementwise: fp32 row-major -> hi/lo bf16 row-major (8 elems / thread)
__global__ __launch_bounds__(256) void split_rm(const float* __restrict__ in,
                                                __nv_bfloat16* __restrict__ oh,
                                                __nv_bfloat16* __restrict__ ol) {
    size_t g = (size_t)(blockIdx.x * 256 + threadIdx.x) * 8;
    float4 v0 = *reinterpret_cast<const float4*>(in + g);
    float4 v1 = *reinterpret_cast<const float4*>(in + g + 4);
    float vv[8] = {v0.x, v0.y, v0.z, v0.w, v1.x, v1.y, v1.z, v1.w};
    union { unsigned short us[8]; uint4 q; } ph, pl;
#pragma unroll
    for (int j = 0; j < 8; ++j) split_bf16(vv[j], ph.us[j], pl.us[j]);
    *reinterpret_cast<uint4*>(oh + g) = ph.q;
    *reinterpret_cast<uint4*>(ol + g) = pl.q;
}

// W [K, N] fp32 row-major -> Wt [N, K] hi/lo bf16 row-major (transpose + split)
__global__ __launch_bounds__(256) void transpose_split(const float* __restrict__ in,
                                                       __nv_bfloat16* __restrict__ oh,
                                                       __nv_bfloat16* __restrict__ ol,
                                                       int K, int N) {
    __shared__ float ts[64][65];
    const int n0 = blockIdx.x * 64;
    const int k0 = blockIdx.y * 64;
    const int tid = threadIdx.x;
#pragma unroll
    for (int i = 0; i < 16; ++i) {
        int idx = tid + i * 256;
        int r = idx >> 6, c = idx & 63;
        ts[r][c] = in[(size_t)(k0 + r) * N + n0 + c];
    }
    __syncthreads();
#pragma unroll
    for (int i = 0; i < 2; ++i) {
        int g = tid + i * 256;
        int nl = g >> 3, kg = g & 7;
        union { unsigned short us[8]; uint4 q; } ph, pl;
#pragma unroll
        for (int j = 0; j < 8; ++j) split_bf16(ts[kg * 8 + j][nl], ph.us[j], pl.us[j]);
        size_t off = (size_t)(n0 + nl) * K + k0 + kg * 8;
        *reinterpret_cast<uint4*>(oh + off) = ph.q;
        *reinterpret_cast<uint4*>(ol + off) = pl.q;
    }
}

// ---------------- GEMM: C = act(A @ B^T + bias) ----------------
// A: [M][K] hi/lo bf16 row-major.  B: [N][K] hi/lo bf16 row-major (k-contiguous).
// 3-stage cp.async pipeline, ldmatrix fragments, split bf16x2 tensor math.
template <bool RELU, bool SPLIT_OUT>
__global__ __launch_bounds__(256) void gemm_ws(
    const __nv_bfloat16* __restrict__ Ah, const __nv_bfloat16* __restrict__ Al,
    const __nv_bfloat16* __restrict__ Bh, const __nv_bfloat16* __restrict__ Bl,
    const float* __restrict__ bias,
    float* __restrict__ Y, __nv_bfloat16* __restrict__ Oh, __nv_bfloat16* __restrict__ Ol,
    int N, int K)
{
    extern __shared__ __align__(1024) char smem[];
    const uint32_t sb = smem_u32(smem);
    const int tid  = threadIdx.x;
    const int lane = tid & 31;
    const int warp = tid >> 5;
    const int warp_m = (warp >> 1) * 32;   // 4 warps along M
    const int warp_n = (warp & 1) * 64;    // 2 warps along N
    const int m0 = blockIdx.y * BM;
    const int n0 = blockIdx.x * BN;

    // per-thread cp.async coords: r = row in tile (0..127), ch = 16B chunk (0..7)
    const int cp_r  = tid >> 1;            // iter i adds 0/64... (see below)
    // fragment lane coords
    const int fr  = lane & 15;             // row within 16-row group
    const int fch = lane >> 4;             // which 16B k-chunk half

    float acc[2][8][4];
#pragma unroll
    for (int mt = 0; mt < 2; ++mt)
#pragma unroll
        for (int nt = 0; nt < 8; ++nt)
#pragma unroll
            for (int i = 0; i < 4; ++i) acc[mt][nt][i] = 0.f;

    const int ntiles = K >> 6;

    // ---- prefetch helper (inlined via lambda-like macro style) ----
    auto prefetch = [&](int s, int kt) {
        const uint32_t stg = sb + s * STG_BYTES;
#pragma unroll
        for (int i = 0; i < 4; ++i) {
            int idx = tid + i * 256;
            int r  = idx >> 3;
            int ch = idx & 7;
            uint32_t soff = (uint32_t)r * 128 + (uint32_t)((ch ^ (r & 7)) * 16);
            size_t ga = (size_t)(m0 + r) * K + kt * 64 + ch * 8;
            size_t gb = (size_t)(n0 + r) * K + kt * 64 + ch * 8;
            CP_ASYNC16(stg + soff,                 (const char*)(Ah + ga));
            CP_ASYNC16(stg + OP_BYTES + soff,      (const char*)(Al + ga));
            CP_ASYNC16(stg + 2 * OP_BYTES + soff,  (const char*)(Bh + gb));
            CP_ASYNC16(stg + 3 * OP_BYTES + soff,  (const char*)(Bl + gb));
        }
    };

#pragma unroll
    for (int s = 0; s < STAGES; ++s) {
        if (s < ntiles) prefetch(s, s);
        CP_COMMIT();
    }

    // precomputed fragment row offsets
    uint32_t ra128[2], ramask[2], rb128[4], rbmask[4];
#pragma unroll
    for (int mt = 0; mt < 2; ++mt) {
        int r = warp_m + mt * 16 + fr;
        ra128[mt] = (uint32_t)r * 128;
        ramask[mt] = (uint32_t)(r & 7);
    }
#pragma unroll
    for (int ng = 0; ng < 4; ++ng) {
        int r = warp_n + ng * 16 + fr;
        rb128[ng] = (uint32_t)r * 128;
        rbmask[ng] = (uint32_t)(r & 7);
    }

    for (int kt = 0; kt < ntiles; ++kt) {
        const int s = kt % STAGES;
        const uint32_t abase = sb + s * STG_BYTES;
        const uint32_t bbase = abase + 2 * OP_BYTES;
        CP_WAIT2();
        __syncthreads();

#pragma unroll
        for (int ks = 0; ks < 4; ++ks) {
            const uint32_t chsel = (uint32_t)(ks * 2) + (uint32_t)fch;
            uint32_t ahf[2][4], alf[2][4];
#pragma unroll
            for (int mt = 0; mt < 2; ++mt) {
                uint32_t off = abase + ra128[mt] + ((chsel ^ ramask[mt]) * 16);
                LDSM4(ahf[mt][0], ahf[mt][1], ahf[mt][2], ahf[mt][3], off);
                LDSM4(alf[mt][0], alf[mt][1], alf[mt][2], alf[mt][3], off + OP_BYTES);
            }
            uint32_t bhf[4][4], blf[4][4];
#pragma unroll
            for (int ng = 0; ng < 4; ++ng) {
                uint32_t off = bbase + rb128[ng] + ((chsel ^ rbmask[ng]) * 16);
                LDSM4(bhf[ng][0], bhf[ng][1], bhf[ng][2], bhf[ng][3], off);
                LDSM4(blf[ng][0], blf[ng][1], blf[ng][2], blf[ng][3], off + OP_BYTES);
            }
#pragma unroll
            for (int mt = 0; mt < 2; ++mt) {
#pragma unroll
                for (int ng = 0; ng < 4; ++ng) {
                    // tile 2*ng   : b regs {f[0], f[2]} ; tile 2*ng+1 : {f[1], f[3]}
                    float* a0 = acc[mt][ng * 2];
                    float* a1 = acc[mt][ng * 2 + 1];
                    mma16816(a0, ahf[mt], bhf[ng][0], bhf[ng][2]);  // hi*hi
                    mma16816(a0, ahf[mt], blf[ng][0], blf[ng][2]);  // hi*lo
                    mma16816(a0, alf[mt], bhf[ng][0], bhf[ng][2]);  // lo*hi
                    mma16816(a1, ahf[mt], bhf[ng][1], bhf[ng][3]);
                    mma16816(a1, ahf[mt], blf[ng][1], blf[ng][3]);
                    mma16816(a1, alf[mt], bhf[ng][1], bhf[ng][3]);
                }
            }
        }
        __syncthreads();
        const int nk = kt + STAGES;
        if (nk < ntiles) prefetch(s, nk);
        CP_COMMIT();
    }

    // ---- epilogue ----
#pragma unroll
    for (int mt = 0; mt < 2; ++mt) {
#pragma unroll
        for (int nt = 0; nt < 8; ++nt) {
            const int r = m0 + warp_m + mt * 16 + (lane >> 2);
            const int c = n0 + warp_n + nt * 8 + (lane & 3) * 2;
            const float bb0 = __ldg(&bias[c]);
            const float bb1 = __ldg(&bias[c + 1]);
            float v0 = acc[mt][nt][0] + bb0;
            float v1 = acc[mt][nt][1] + bb1;
            float v2 = acc[mt][nt][2] + bb0;
            float v3 = acc[mt][nt][3] + bb1;
            if (RELU) {
                v0 = fmaxf(v0, 0.f); v1 = fmaxf(v1, 0.f);
                v2 = fmaxf(v2, 0.f); v3 = fmaxf(v3, 0.f);
            }
            if (SPLIT_OUT) {
                unsigned short h0, l0, h1, l1, h2, l2, h3, l3;
                split_bf16(v0, h0, l0); split_bf16(v1, h1, l1);
                split_bf16(v2, h2, l2); split_bf16(v3, h3, l3);
                *reinterpret_cast<uint32_t*>(Oh + (size_t)r * N + c) =
                    (uint32_t)h0 | ((uint32_t)h1 << 16);
                *reinterpret_cast<uint32_t*>(Ol + (size_t)r * N + c) =
                    (uint32_t)l0 | ((uint32_t)l1 << 16);
                *reinterpret_cast<uint32_t*>(Oh + (size_t)(r + 8) * N + c) =
                    (uint32_t)h2 | ((uint32_t)h3 << 16);
                *reinterpret_cast<uint32_t*>(Ol + (size_t)(r + 8) * N + c) =
                    (uint32_t)l2 | ((uint32_t)l3 << 16);
            } else {
                *reinterpret_cast<float2*>(&Y[(size_t)r * N + c]) = make_float2(v0, v1);
                *reinterpret_cast<float2*>(&Y[(size_t)(r + 8) * N + c]) = make_float2(v2, v3);
            }
        }
    }
}

// ---------------- Host launch ----------------
extern "C" void kernel_launch(void* const* d_in, const int* in_sizes, int n_in,
                              void* d_out, int out_size) {
    const float* x  = (const float*)d_in[0];
    const float* W1 = (const float*)d_in[1];
    const float* b1 = (const float*)d_in[2];
    const float* W2 = (const float*)d_in[3];
    const float* b2 = (const float*)d_in[4];
    float* y = (float*)d_out;

    __nv_bfloat16 *xh, *xl, *w1h, *w1l, *w2h, *w2l, *hh, *hl;
    cudaGetSymbolAddress((void**)&xh,  g_xh);
    cudaGetSymbolAddress((void**)&xl,  g_xl);
    cudaGetSymbolAddress((void**)&w1h, g_w1h);
    cudaGetSymbolAddress((void**)&w1l, g_w1l);
    cudaGetSymbolAddress((void**)&w2h, g_w2h);
    cudaGetSymbolAddress((void**)&w2l, g_w2l);
    cudaGetSymbolAddress((void**)&hh,  g_hh);
    cudaGetSymbolAddress((void**)&hl,  g_hl);

    cudaFuncSetAttribute(gemm_ws<true, true>,
                         cudaFuncAttributeMaxDynamicSharedMemorySize, SMEM_TOTAL);
    cudaFuncSetAttribute(gemm_ws<false, false>,
                         cudaFuncAttributeMaxDynamicSharedMemorySize, SMEM_TOTAL);

    // Pre-split inputs (x elementwise; weights transposed to [N][K])
    split_rm<<<(B_DIM * N_IN / 8) / 256, 256>>>(x, xh, xl);
    transpose_split<<<dim3(N_HID / 64, N_IN / 64), 256>>>(W1, w1h, w1l, N_IN, N_HID);
    transpose_split<<<dim3(N_OUT / 64, N_HID / 64), 256>>>(W2, w2h, w2l, N_HID, N_OUT);

    // GEMM1: h = relu(x @ W1 + b1) -> pre-split hi/lo bf16
    gemm_ws<true, true><<<dim3(N_HID / BN, B_DIM / BM), 256, SMEM_TOTAL>>>(
        xh, xl, w1h, w1l, b1, nullptr, hh, hl, N_HID, N_IN);

    // GEMM2: y = h @ W2 + b2 (fp32 out)
    gemm_ws<false, false><<<dim3(N_OUT / BN, B_DIM / BM), 256, SMEM_TOTAL>>>(
        hh, hl, w2h, w2l, b2, y, nullptr, nullptr, N_OUT, N_HID);
}

// round 4
// speedup vs baseline: 4.2702x; 1.3642x over previous
#include <cuda_runtime.h>
#include <cuda_fp16.h>
#include <stdint.h>

// ---------------- Problem dims ----------------
#define B_DIM  4096
#define N_IN   1024
#define N_HID  4096
#define N_OUT  1024

// ---------------- GEMM tiling ----------------
#define BM 128
#define BN 256
#define BK 64                  // fp16 elems per stage -> 128B rows (xor swizzle)
#define STAGES 3
#define NTHR 512
#define A_HALF   (BM * 128)              // 16384 B per A half (hi or lo)
#define B_BYTES  (BN * 128)              // 32768 B
#define STG_BYTES (2 * A_HALF + B_BYTES) // 65536
#define SMEM_TOTAL (STAGES * STG_BYTES)  // 196608

// ---------------- Device scratch (allocation-free rule) ----------------
__device__ __align__(128) __half g_xh[(size_t)B_DIM * N_IN];
__device__ __align__(128) __half g_xl[(size_t)B_DIM * N_IN];
__device__ __align__(128) __half g_w1[(size_t)N_HID * N_IN];    // [N][K] single fp16
__device__ __align__(128) __half g_w2[(size_t)N_OUT * N_HID];   // [N][K] single fp16
__device__ __align__(128) __half g_hh[(size_t)B_DIM * N_HID];
__device__ __align__(128) __half g_hl[(size_t)B_DIM * N_HID];

// ---------------- PTX helpers ----------------
__device__ __forceinline__ uint32_t smem_u32(const void* p) {
    uint32_t a;
    asm("{ .reg .u64 t; cvta.to.shared.u64 t, %1; cvt.u32.u64 %0, t; }" : "=r"(a) : "l"(p));
    return a;
}
#define CP_ASYNC16(dst, src) \
    asm volatile("cp.async.cg.shared.global [%0], [%1], 16;" :: "r"(dst), "l"(src))
#define CP_COMMIT() asm volatile("cp.async.commit_group;" ::: "memory")
#define CP_WAIT()   asm volatile("cp.async.wait_group %0;" :: "n"(STAGES - 1) : "memory")

#define LDSM4(r0, r1, r2, r3, a) \
    asm volatile("ldmatrix.sync.aligned.m8n8.x4.shared.b16 {%0,%1,%2,%3}, [%4];" \
                 : "=r"(r0), "=r"(r1), "=r"(r2), "=r"(r3) : "r"(a))

__device__ __forceinline__ void mma16816(float* d, const uint32_t* a, uint32_t b0, uint32_t b1) {
    asm volatile(
        "mma.sync.aligned.m16n8k16.row.col.f32.f16.f16.f32 "
        "{%0,%1,%2,%3}, {%4,%5,%6,%7}, {%8,%9}, {%0,%1,%2,%3};\n"
        : "+f"(d[0]), "+f"(d[1]), "+f"(d[2]), "+f"(d[3])
        : "r"(a[0]), "r"(a[1]), "r"(a[2]), "r"(a[3]), "r"(b0), "r"(b1));
}

__device__ __forceinline__ void split_f16(float v, unsigned short& h, unsigned short& l) {
    __half hb = __float2half_rn(v);
    __half lb = __float2half_rn(v - __half2float(hb));
    h = __half_as_ushort(hb);
    l = __half_as_ushort(lb);
}

// ---------------- Convert kernels ----------------

// fp32 row-major -> hi/lo fp16 pair, row-major (8 elems / thread)
__global__ __launch_bounds__(256) void split_pair(const float* __restrict__ in,
                                                  __half* __restrict__ oh,
                                                  __half* __restrict__ ol) {
    size_t g = (size_t)(blockIdx.x * 256 + threadIdx.x) * 8;
    float4 v0 = *reinterpret_cast<const float4*>(in + g);
    float4 v1 = *reinterpret_cast<const float4*>(in + g + 4);
    float vv[8] = {v0.x, v0.y, v0.z, v0.w, v1.x, v1.y, v1.z, v1.w};
    union { unsigned short us[8]; uint4 q; } ph, pl;
#pragma unroll
    for (int j = 0; j < 8; ++j) split_f16(vv[j], ph.us[j], pl.us[j]);
    *reinterpret_cast<uint4*>(oh + g) = ph.q;
    *reinterpret_cast<uint4*>(ol + g) = pl.q;
}

// W [K, N] fp32 row-major -> Wt [N, K] single fp16 row-major
__global__ __launch_bounds__(256) void transpose_f16(const float* __restrict__ in,
                                                     __half* __restrict__ out,
                                                     int K, int N) {
    __shared__ float ts[64][65];
    const int n0 = blockIdx.x * 64;
    const int k0 = blockIdx.y * 64;
    const int tid = threadIdx.x;
#pragma unroll
    for (int i = 0; i < 16; ++i) {
        int idx = tid + i * 256;
        int r = idx >> 6, c = idx & 63;
        ts[r][c] = in[(size_t)(k0 + r) * N + n0 + c];
    }
    __syncthreads();
#pragma unroll
    for (int i = 0; i < 2; ++i) {
        int g = tid + i * 256;
        int nl = g >> 3, kg = g & 7;
        union { unsigned short us[8]; uint4 q; } p;
#pragma unroll
        for (int j = 0; j < 8; ++j)
            p.us[j] = __half_as_ushort(__float2half_rn(ts[kg * 8 + j][nl]));
        *reinterpret_cast<uint4*>(out + (size_t)(n0 + nl) * K + k0 + kg * 8) = p.q;
    }
}

// ---------------- GEMM: C = act(A @ B^T + bias) ----------------
// A: [M][K] fp16 hi/lo pair, row-major.  B: [N][K] single fp16, row-major.
// D = Ah*B + Al*B  (2 MMAs per product), fp32 accumulate.
template <bool RELU, bool SPLIT_OUT>
__global__ __launch_bounds__(NTHR, 1) void gemm_f16p(
    const __half* __restrict__ Ah, const __half* __restrict__ Al,
    const __half* __restrict__ Bw,
    const float* __restrict__ bias,
    float* __restrict__ Y, __half* __restrict__ Oh, __half* __restrict__ Ol,
    int N, int K)
{
    extern __shared__ __align__(1024) char smem[];
    const uint32_t sb = smem_u32(smem);
    const int tid  = threadIdx.x;
    const int lane = tid & 31;
    const int warp = tid >> 5;
    const int warp_m = (warp & 3) * 32;    // 4 warps along M
    const int warp_n = (warp >> 2) * 64;   // 4 warps along N
    const int m0 = blockIdx.y * BM;
    const int n0 = blockIdx.x * BN;

    const int fr  = lane & 15;             // ldmatrix row within 16-group
    const int fch = lane >> 4;             // 16B k-chunk half

    float acc[2][8][4];
#pragma unroll
    for (int mt = 0; mt < 2; ++mt)
#pragma unroll
        for (int nt = 0; nt < 8; ++nt)
#pragma unroll
            for (int i = 0; i < 4; ++i) acc[mt][nt][i] = 0.f;

    const int ntiles = K >> 6;

    // prefetch: A chunks 1024 per half (2 iters @512thr), B chunks 2048 (4 iters)
    auto prefetch = [&](int s, int kt) {
        const uint32_t stg = sb + s * STG_BYTES;
        const int kof = kt * 64;
#pragma unroll
        for (int i = 0; i < 2; ++i) {
            int idx = tid + i * NTHR;
            int r = idx >> 3, ch = idx & 7;
            uint32_t soff = (uint32_t)r * 128 + (uint32_t)((ch ^ (r & 7)) * 16);
            size_t ga = (size_t)(m0 + r) * K + kof + ch * 8;
            CP_ASYNC16(stg + soff,          (const char*)(Ah + ga));
            CP_ASYNC16(stg + A_HALF + soff, (const char*)(Al + ga));
        }
#pragma unroll
        for (int i = 0; i < 4; ++i) {
            int idx = tid + i * NTHR;
            int r = idx >> 3, ch = idx & 7;
            uint32_t soff = (uint32_t)r * 128 + (uint32_t)((ch ^ (r & 7)) * 16);
            size_t gb = (size_t)(n0 + r) * K + kof + ch * 8;
            CP_ASYNC16(stg + 2 * A_HALF + soff, (const char*)(Bw + gb));
        }
    };

#pragma unroll
    for (int s = 0; s < STAGES; ++s) {
        if (s < ntiles) prefetch(s, s);
        CP_COMMIT();
    }

    // precomputed fragment row offsets
    uint32_t ra128[2], ramask[2], rb128[4], rbmask[4];
#pragma unroll
    for (int mt = 0; mt < 2; ++mt) {
        int r = warp_m + mt * 16 + fr;
        ra128[mt] = (uint32_t)r * 128;
        ramask[mt] = (uint32_t)(r & 7);
    }
#pragma unroll
    for (int ng = 0; ng < 4; ++ng) {
        int r = warp_n + ng * 16 + fr;
        rb128[ng] = (uint32_t)r * 128;
        rbmask[ng] = (uint32_t)(r & 7);
    }

    for (int kt = 0; kt < ntiles; ++kt) {
        const int s = kt % STAGES;
        const uint32_t abase = sb + s * STG_BYTES;
        const uint32_t bbase = abase + 2 * A_HALF;
        CP_WAIT();
        __syncthreads();

#pragma unroll
        for (int ks = 0; ks < 4; ++ks) {
            const uint32_t chsel = (uint32_t)(ks * 2) + (uint32_t)fch;
            uint32_t ahf[2][4], alf[2][4];
#pragma unroll
            for (int mt = 0; mt < 2; ++mt) {
                uint32_t off = abase + ra128[mt] + ((chsel ^ ramask[mt]) * 16);
                LDSM4(ahf[mt][0], ahf[mt][1], ahf[mt][2], ahf[mt][3], off);
                LDSM4(alf[mt][0], alf[mt][1], alf[mt][2], alf[mt][3], off + A_HALF);
            }
            uint32_t bf[4][4];
#pragma unroll
            for (int ng = 0; ng < 4; ++ng) {
                uint32_t off = bbase + rb128[ng] + ((chsel ^ rbmask[ng]) * 16);
                LDSM4(bf[ng][0], bf[ng][1], bf[ng][2], bf[ng][3], off);
            }
#pragma unroll
            for (int mt = 0; mt < 2; ++mt) {
#pragma unroll
                for (int ng = 0; ng < 4; ++ng) {
                    float* a0 = acc[mt][ng * 2];
                    float* a1 = acc[mt][ng * 2 + 1];
                    mma16816(a0, ahf[mt], bf[ng][0], bf[ng][2]);
                    mma16816(a0, alf[mt], bf[ng][0], bf[ng][2]);
                    mma16816(a1, ahf[mt], bf[ng][1], bf[ng][3]);
                    mma16816(a1, alf[mt], bf[ng][1], bf[ng][3]);
                }
            }
        }
        __syncthreads();
        const int nk = kt + STAGES;
        if (nk < ntiles) prefetch(s, nk);
        CP_COMMIT();
    }

    // ---- epilogue ----
#pragma unroll
    for (int mt = 0; mt < 2; ++mt) {
#pragma unroll
        for (int nt = 0; nt < 8; ++nt) {
            const int r = m0 + warp_m + mt * 16 + (lane >> 2);
            const int c = n0 + warp_n + nt * 8 + (lane & 3) * 2;
            const float bb0 = __ldg(&bias[c]);
            const float bb1 = __ldg(&bias[c + 1]);
            float v0 = acc[mt][nt][0] + bb0;
            float v1 = acc[mt][nt][1] + bb1;
            float v2 = acc[mt][nt][2] + bb0;
            float v3 = acc[mt][nt][3] + bb1;
            if (RELU) {
                v0 = fmaxf(v0, 0.f); v1 = fmaxf(v1, 0.f);
                v2 = fmaxf(v2, 0.f); v3 = fmaxf(v3, 0.f);
            }
            if (SPLIT_OUT) {
                unsigned short h0, l0, h1, l1, h2, l2, h3, l3;
                split_f16(v0, h0, l0); split_f16(v1, h1, l1);
                split_f16(v2, h2, l2); split_f16(v3, h3, l3);
                *reinterpret_cast<uint32_t*>(Oh + (size_t)r * N + c) =
                    (uint32_t)h0 | ((uint32_t)h1 << 16);
                *reinterpret_cast<uint32_t*>(Ol + (size_t)r * N + c) =
                    (uint32_t)l0 | ((uint32_t)l1 << 16);
                *reinterpret_cast<uint32_t*>(Oh + (size_t)(r + 8) * N + c) =
                    (uint32_t)h2 | ((uint32_t)h3 << 16);
                *reinterpret_cast<uint32_t*>(Ol + (size_t)(r + 8) * N + c) =
                    (uint32_t)l2 | ((uint32_t)l3 << 16);
            } else {
                *reinterpret_cast<float2*>(&Y[(size_t)r * N + c]) = make_float2(v0, v1);
                *reinterpret_cast<float2*>(&Y[(size_t)(r + 8) * N + c]) = make_float2(v2, v3);
            }
        }
    }
}

// ---------------- Host launch ----------------
extern "C" void kernel_launch(void* const* d_in, const int* in_sizes, int n_in,
                              void* d_out, int out_size) {
    const float* x  = (const float*)d_in[0];
    const float* W1 = (const float*)d_in[1];
    const float* b1 = (const float*)d_in[2];
    const float* W2 = (const float*)d_in[3];
    const float* b2 = (const float*)d_in[4];
    float* y = (float*)d_out;

    __half *xh, *xl, *w1, *w2, *hh, *hl;
    cudaGetSymbolAddress((void**)&xh, g_xh);
    cudaGetSymbolAddress((void**)&xl, g_xl);
    cudaGetSymbolAddress((void**)&w1, g_w1);
    cudaGetSymbolAddress((void**)&w2, g_w2);
    cudaGetSymbolAddress((void**)&hh, g_hh);
    cudaGetSymbolAddress((void**)&hl, g_hl);

    cudaFuncSetAttribute(gemm_f16p<true, true>,
                         cudaFuncAttributeMaxDynamicSharedMemorySize, SMEM_TOTAL);
    cudaFuncSetAttribute(gemm_f16p<false, false>,
                         cudaFuncAttributeMaxDynamicSharedMemorySize, SMEM_TOTAL);

    // Pre-split x into fp16 pair; transpose weights to [N][K] single fp16
    split_pair<<<(B_DIM * N_IN / 8) / 256, 256>>>(x, xh, xl);
    transpose_f16<<<dim3(N_HID / 64, N_IN / 64), 256>>>(W1, w1, N_IN, N_HID);
    transpose_f16<<<dim3(N_OUT / 64, N_HID / 64), 256>>>(W2, w2, N_HID, N_OUT);

    // GEMM1: h = relu(x @ W1 + b1) -> fp16 pair
    gemm_f16p<true, true><<<dim3(N_HID / BN, B_DIM / BM), NTHR, SMEM_TOTAL>>>(
        xh, xl, w1, b1, nullptr, hh, hl, N_HID, N_IN);

    // GEMM2: y = h @ W2 + b2 (fp32 out)
    gemm_f16p<false, false><<<dim3(N_OUT / BN, B_DIM / BM), NTHR, SMEM_TOTAL>>>(
        hh, hl, w2, b2, y, nullptr, nullptr, N_OUT, N_HID);
}

// round 5
// speedup vs baseline: 7.4118x; 1.7357x over previous
#include <cuda_runtime.h>
#include <cuda_fp16.h>
#include <stdint.h>

// ---------------- Problem dims ----------------
#define B_DIM  4096
#define N_IN   1024
#define N_HID  4096
#define N_OUT  1024

// ---------------- GEMM tiling ----------------
#define BN 256
#define BK 64                  // fp16 elems per stage -> 128B rows (xor swizzle)
#define SLOTS 4                // smem slots; 3 in flight
#define NTHR 512

// ---------------- Device scratch (allocation-free rule) ----------------
__device__ __align__(128) __half g_xf[(size_t)B_DIM * N_IN];
__device__ __align__(128) __half g_w1[(size_t)N_HID * N_IN];    // [N][K]
__device__ __align__(128) __half g_w2[(size_t)N_OUT * N_HID];   // [N][K]
__device__ __align__(128) __half g_hf[(size_t)B_DIM * N_HID];

// ---------------- PTX helpers ----------------
__device__ __forceinline__ uint32_t smem_u32(const void* p) {
    uint32_t a;
    asm("{ .reg .u64 t; cvta.to.shared.u64 t, %1; cvt.u32.u64 %0, t; }" : "=r"(a) : "l"(p));
    return a;
}
#define CP_ASYNC16(dst, src) \
    asm volatile("cp.async.cg.shared.global [%0], [%1], 16;" :: "r"(dst), "l"(src))
#define CP_COMMIT() asm volatile("cp.async.commit_group;" ::: "memory")
#define CP_WAIT2()  asm volatile("cp.async.wait_group 2;" ::: "memory")

#define LDSM4(r0, r1, r2, r3, a) \
    asm volatile("ldmatrix.sync.aligned.m8n8.x4.shared.b16 {%0,%1,%2,%3}, [%4];" \
                 : "=r"(r0), "=r"(r1), "=r"(r2), "=r"(r3) : "r"(a))

__device__ __forceinline__ void mma16816(float* d, const uint32_t* a, uint32_t b0, uint32_t b1) {
    asm volatile(
        "mma.sync.aligned.m16n8k16.row.col.f32.f16.f16.f32 "
        "{%0,%1,%2,%3}, {%4,%5,%6,%7}, {%8,%9}, {%0,%1,%2,%3};\n"
        : "+f"(d[0]), "+f"(d[1]), "+f"(d[2]), "+f"(d[3])
        : "r"(a[0]), "r"(a[1]), "r"(a[2]), "r"(a[3]), "r"(b0), "r"(b1));
}

// ---------------- Convert kernels ----------------

// fp32 -> fp16, row-major (8 elems / thread)
__global__ __launch_bounds__(256) void cvt_f16(const float* __restrict__ in,
                                               __half* __restrict__ out) {
    size_t g = (size_t)(blockIdx.x * 256 + threadIdx.x) * 8;
    float4 v0 = *reinterpret_cast<const float4*>(in + g);
    float4 v1 = *reinterpret_cast<const float4*>(in + g + 4);
    float vv[8] = {v0.x, v0.y, v0.z, v0.w, v1.x, v1.y, v1.z, v1.w};
    union { unsigned short us[8]; uint4 q; } p;
#pragma unroll
    for (int j = 0; j < 8; ++j) p.us[j] = __half_as_ushort(__float2half_rn(vv[j]));
    *reinterpret_cast<uint4*>(out + g) = p.q;
}

// W [K, N] fp32 row-major -> Wt [N, K] fp16 row-major
__global__ __launch_bounds__(256) void transpose_f16(const float* __restrict__ in,
                                                     __half* __restrict__ out,
                                                     int K, int N) {
    __shared__ float ts[64][65];
    const int n0 = blockIdx.x * 64;
    const int k0 = blockIdx.y * 64;
    const int tid = threadIdx.x;
#pragma unroll
    for (int i = 0; i < 16; ++i) {
        int idx = tid + i * 256;
        int r = idx >> 6, c = idx & 63;
        ts[r][c] = in[(size_t)(k0 + r) * N + n0 + c];
    }
    __syncthreads();
#pragma unroll
    for (int i = 0; i < 2; ++i) {
        int g = tid + i * 256;
        int nl = g >> 3, kg = g & 7;
        union { unsigned short us[8]; uint4 q; } p;
#pragma unroll
        for (int j = 0; j < 8; ++j)
            p.us[j] = __half_as_ushort(__float2half_rn(ts[kg * 8 + j][nl]));
        *reinterpret_cast<uint4*>(out + (size_t)(n0 + nl) * K + k0 + kg * 8) = p.q;
    }
}

// ---------------- GEMM: C = act(A @ B^T + bias) ----------------
// A: [M][K] fp16 row-major.  B: [N][K] fp16 row-major (k-contiguous).
// 4-slot / 3-in-flight cp.async pipeline, ONE __syncthreads per k-tile.
// BMv in {128, 64}: warp grid (BMv/32) x (16/(BMv/32)); warp tile 32 x (BN/warps_n).
template <int BMv, bool RELU, bool F16_OUT>
__global__ __launch_bounds__(NTHR, 1) void gemm_f16(
    const __half* __restrict__ A, const __half* __restrict__ Bw,
    const float* __restrict__ bias,
    float* __restrict__ Y, __half* __restrict__ Oh,
    int N, int K)
{
    constexpr int WARPS_M = BMv / 32;            // 4 or 2
    constexpr int WARPS_N = 16 / WARPS_M;        // 4 or 8
    constexpr int WNW     = BN / WARPS_N;        // 64 or 32 (warp n-width)
    constexpr int NT      = WNW / 8;             // 8 or 4 n-tiles
    constexpr int NG      = NT / 2;              // 4 or 2 ldmatrix n-groups
    constexpr int A_BYTES = BMv * 128;
    constexpr int STG     = A_BYTES + BN * 128;  // stage bytes
    constexpr int A_ITERS = (BMv * 8) / NTHR;    // 2 or 1
    constexpr int B_ITERS = (BN * 8) / NTHR;     // 4

    extern __shared__ __align__(1024) char smem[];
    const uint32_t sb = smem_u32(smem);
    const int tid  = threadIdx.x;
    const int lane = tid & 31;
    const int warp = tid >> 5;
    const int warp_m = (warp % WARPS_M) * 32;
    const int warp_n = (warp / WARPS_M) * WNW;
    const int m0 = blockIdx.y * BMv;
    const int n0 = blockIdx.x * BN;

    const int fr  = lane & 15;
    const int fch = lane >> 4;

    float acc[2][NT][4];
#pragma unroll
    for (int mt = 0; mt < 2; ++mt)
#pragma unroll
        for (int nt = 0; nt < NT; ++nt)
#pragma unroll
            for (int i = 0; i < 4; ++i) acc[mt][nt][i] = 0.f;

    const int ntiles = K >> 6;

    auto prefetch = [&](int s, int kt) {
        const uint32_t stg = sb + s * STG;
        const int kof = kt * 64;
#pragma unroll
        for (int i = 0; i < A_ITERS; ++i) {
            int idx = tid + i * NTHR;
            int r = idx >> 3, ch = idx & 7;
            uint32_t soff = (uint32_t)r * 128 + (uint32_t)((ch ^ (r & 7)) * 16);
            CP_ASYNC16(stg + soff, (const char*)(A + (size_t)(m0 + r) * K + kof + ch * 8));
        }
#pragma unroll
        for (int i = 0; i < B_ITERS; ++i) {
            int idx = tid + i * NTHR;
            int r = idx >> 3, ch = idx & 7;
            uint32_t soff = (uint32_t)r * 128 + (uint32_t)((ch ^ (r & 7)) * 16);
            CP_ASYNC16(stg + A_BYTES + soff,
                       (const char*)(Bw + (size_t)(n0 + r) * K + kof + ch * 8));
        }
    };

    // 3 stages in flight
#pragma unroll
    for (int s = 0; s < 3; ++s) {
        if (s < ntiles) prefetch(s, s);
        CP_COMMIT();
    }

    // precomputed fragment row offsets
    uint32_t ra128[2], ramask[2], rb128[NG], rbmask[NG];
#pragma unroll
    for (int mt = 0; mt < 2; ++mt) {
        int r = warp_m + mt * 16 + fr;
        ra128[mt] = (uint32_t)r * 128;
        ramask[mt] = (uint32_t)(r & 7);
    }
#pragma unroll
    for (int ng = 0; ng < NG; ++ng) {
        int r = warp_n + ng * 16 + fr;
        rb128[ng] = (uint32_t)r * 128;
        rbmask[ng] = (uint32_t)(r & 7);
    }

    for (int kt = 0; kt < ntiles; ++kt) {
        const int s = kt & (SLOTS - 1);
        const uint32_t abase = sb + s * STG;
        const uint32_t bbase = abase + A_BYTES;

        CP_WAIT2();            // tile kt's group complete (3 in flight)
        __syncthreads();       // all warps done with iter kt-1 -> safe to refill its slot

        const int nk = kt + 3;
        if (nk < ntiles) prefetch((kt + 3) & (SLOTS - 1), nk);
        CP_COMMIT();

#pragma unroll
        for (int ks = 0; ks < 4; ++ks) {
            const uint32_t chsel = (uint32_t)(ks * 2) + (uint32_t)fch;
            uint32_t af[2][4];
#pragma unroll
            for (int mt = 0; mt < 2; ++mt) {
                uint32_t off = abase + ra128[mt] + ((chsel ^ ramask[mt]) * 16);
                LDSM4(af[mt][0], af[mt][1], af[mt][2], af[mt][3], off);
            }
            uint32_t bf[NG][4];
#pragma unroll
            for (int ng = 0; ng < NG; ++ng) {
                uint32_t off = bbase + rb128[ng] + ((chsel ^ rbmask[ng]) * 16);
                LDSM4(bf[ng][0], bf[ng][1], bf[ng][2], bf[ng][3], off);
            }
#pragma unroll
            for (int mt = 0; mt < 2; ++mt) {
#pragma unroll
                for (int ng = 0; ng < NG; ++ng) {
                    mma16816(acc[mt][ng * 2],     af[mt], bf[ng][0], bf[ng][2]);
                    mma16816(acc[mt][ng * 2 + 1], af[mt], bf[ng][1], bf[ng][3]);
                }
            }
        }
    }

    // ---- epilogue ----
#pragma unroll
    for (int mt = 0; mt < 2; ++mt) {
#pragma unroll
        for (int nt = 0; nt < NT; ++nt) {
            const int r = m0 + warp_m + mt * 16 + (lane >> 2);
            const int c = n0 + warp_n + nt * 8 + (lane & 3) * 2;
            const float bb0 = __ldg(&bias[c]);
            const float bb1 = __ldg(&bias[c + 1]);
            float v0 = acc[mt][nt][0] + bb0;
            float v1 = acc[mt][nt][1] + bb1;
            float v2 = acc[mt][nt][2] + bb0;
            float v3 = acc[mt][nt][3] + bb1;
            if (RELU) {
                v0 = fmaxf(v0, 0.f); v1 = fmaxf(v1, 0.f);
                v2 = fmaxf(v2, 0.f); v3 = fmaxf(v3, 0.f);
            }
            if (F16_OUT) {
                __half2 p0 = __floats2half2_rn(v0, v1);
                __half2 p1 = __floats2half2_rn(v2, v3);
                *reinterpret_cast<__half2*>(Oh + (size_t)r * N + c) = p0;
                *reinterpret_cast<__half2*>(Oh + (size_t)(r + 8) * N + c) = p1;
            } else {
                *reinterpret_cast<float2*>(&Y[(size_t)r * N + c]) = make_float2(v0, v1);
                *reinterpret_cast<float2*>(&Y[(size_t)(r + 8) * N + c]) = make_float2(v2, v3);
            }
        }
    }
}

// ---------------- Host launch ----------------
#define SMEM_G1 (SLOTS * (128 * 128 + BN * 128))   // 4 * 48K = 192K
#define SMEM_G2 (SLOTS * (64 * 128 + BN * 128))    // 4 * 40K = 160K

extern "C" void kernel_launch(void* const* d_in, const int* in_sizes, int n_in,
                              void* d_out, int out_size) {
    const float* x  = (const float*)d_in[0];
    const float* W1 = (const float*)d_in[1];
    const float* b1 = (const float*)d_in[2];
    const float* W2 = (const float*)d_in[3];
    const float* b2 = (const float*)d_in[4];
    float* y = (float*)d_out;

    __half *xf, *w1, *w2, *hf;
    cudaGetSymbolAddress((void**)&xf, g_xf);
    cudaGetSymbolAddress((void**)&w1, g_w1);
    cudaGetSymbolAddress((void**)&w2, g_w2);
    cudaGetSymbolAddress((void**)&hf, g_hf);

    cudaFuncSetAttribute(gemm_f16<128, true, true>,
                         cudaFuncAttributeMaxDynamicSharedMemorySize, SMEM_G1);
    cudaFuncSetAttribute(gemm_f16<64, false, false>,
                         cudaFuncAttributeMaxDynamicSharedMemorySize, SMEM_G2);

    // Converts
    cvt_f16<<<(B_DIM * N_IN / 8) / 256, 256>>>(x, xf);
    transpose_f16<<<dim3(N_HID / 64, N_IN / 64), 256>>>(W1, w1, N_IN, N_HID);
    transpose_f16<<<dim3(N_OUT / 64, N_HID / 64), 256>>>(W2, w2, N_HID, N_OUT);

    // GEMM1: h = relu(x @ W1 + b1) -> fp16   (grid 16 x 32 = 512 CTAs)
    gemm_f16<128, true, true><<<dim3(N_HID / BN, B_DIM / 128), NTHR, SMEM_G1>>>(
        xf, w1, b1, nullptr, hf, N_HID, N_IN);

    // GEMM2: y = h @ W2 + b2 (fp32 out)      (grid 4 x 64 = 256 CTAs)
    gemm_f16<64, false, false><<<dim3(N_OUT / BN, B_DIM / 64), NTHR, SMEM_G2>>>(
        hf, w2, b2, y, nullptr, N_OUT, N_HID);
}

// round 6
// speedup vs baseline: 8.2557x; 1.1139x over previous
#include <cuda_runtime.h>
#include <cuda_fp16.h>
#include <stdint.h>

// ---------------- Problem dims ----------------
#define B_DIM  4096
#define N_IN   1024
#define N_HID  4096
#define N_OUT  1024

// ---------------- GEMM tiling ----------------
#define BN 128
#define BK 64                  // fp16 elems per stage -> 128B rows (xor swizzle)
#define SLOTS 3                // smem slots; 2 in flight
#define NTHR 256

// ---------------- Device scratch (allocation-free rule) ----------------
__device__ __align__(128) __half g_xf[(size_t)B_DIM * N_IN];
__device__ __align__(128) __half g_w1[(size_t)N_HID * N_IN];    // [N][K]
__device__ __align__(128) __half g_w2[(size_t)N_OUT * N_HID];   // [N][K]
__device__ __align__(128) __half g_hf[(size_t)B_DIM * N_HID];

// ---------------- PTX helpers ----------------
__device__ __forceinline__ uint32_t smem_u32(const void* p) {
    uint32_t a;
    asm("{ .reg .u64 t; cvta.to.shared.u64 t, %1; cvt.u32.u64 %0, t; }" : "=r"(a) : "l"(p));
    return a;
}
#define CP_ASYNC16(dst, src) \
    asm volatile("cp.async.cg.shared.global [%0], [%1], 16;" :: "r"(dst), "l"(src))
#define CP_COMMIT() asm volatile("cp.async.commit_group;" ::: "memory")
#define CP_WAIT1()  asm volatile("cp.async.wait_group 1;" ::: "memory")

#define LDSM4(r0, r1, r2, r3, a) \
    asm volatile("ldmatrix.sync.aligned.m8n8.x4.shared.b16 {%0,%1,%2,%3}, [%4];" \
                 : "=r"(r0), "=r"(r1), "=r"(r2), "=r"(r3) : "r"(a))

__device__ __forceinline__ void mma16816(float* d, const uint32_t* a, uint32_t b0, uint32_t b1) {
    asm volatile(
        "mma.sync.aligned.m16n8k16.row.col.f32.f16.f16.f32 "
        "{%0,%1,%2,%3}, {%4,%5,%6,%7}, {%8,%9}, {%0,%1,%2,%3};\n"
        : "+f"(d[0]), "+f"(d[1]), "+f"(d[2]), "+f"(d[3])
        : "r"(a[0]), "r"(a[1]), "r"(a[2]), "r"(a[3]), "r"(b0), "r"(b1));
}

// ---------------- Convert kernels ----------------

// fp32 -> fp16, row-major (8 elems / thread)
__global__ __launch_bounds__(256) void cvt_f16(const float* __restrict__ in,
                                               __half* __restrict__ out) {
    size_t g = (size_t)(blockIdx.x * 256 + threadIdx.x) * 8;
    float4 v0 = *reinterpret_cast<const float4*>(in + g);
    float4 v1 = *reinterpret_cast<const float4*>(in + g + 4);
    float vv[8] = {v0.x, v0.y, v0.z, v0.w, v1.x, v1.y, v1.z, v1.w};
    union { unsigned short us[8]; uint4 q; } p;
#pragma unroll
    for (int j = 0; j < 8; ++j) p.us[j] = __half_as_ushort(__float2half_rn(vv[j]));
    *reinterpret_cast<uint4*>(out + g) = p.q;
}

// W [K, N] fp32 row-major -> Wt [N, K] fp16 row-major
__global__ __launch_bounds__(256) void transpose_f16(const float* __restrict__ in,
                                                     __half* __restrict__ out,
                                                     int K, int N) {
    __shared__ float ts[64][65];
    const int n0 = blockIdx.x * 64;
    const int k0 = blockIdx.y * 64;
    const int tid = threadIdx.x;
#pragma unroll
    for (int i = 0; i < 16; ++i) {
        int idx = tid + i * 256;
        int r = idx >> 6, c = idx & 63;
        ts[r][c] = in[(size_t)(k0 + r) * N + n0 + c];
    }
    __syncthreads();
#pragma unroll
    for (int i = 0; i < 2; ++i) {
        int g = tid + i * 256;
        int nl = g >> 3, kg = g & 7;
        union { unsigned short us[8]; uint4 q; } p;
#pragma unroll
        for (int j = 0; j < 8; ++j)
            p.us[j] = __half_as_ushort(__float2half_rn(ts[kg * 8 + j][nl]));
        *reinterpret_cast<uint4*>(out + (size_t)(n0 + nl) * K + k0 + kg * 8) = p.q;
    }
}

// ---------------- GEMM: C = act(A @ B^T + bias) ----------------
// A: [M][K] fp16 row-major.  B: [N][K] fp16 row-major (k-contiguous).
// 256 threads / 8 warps; 2 CTAs per SM; 3-slot, 2-deep cp.async pipeline,
// one __syncthreads per k-tile.
template <int BMv, bool RELU, bool F16_OUT>
__global__ __launch_bounds__(NTHR, 2) void gemm_f16(
    const __half* __restrict__ A, const __half* __restrict__ Bw,
    const float* __restrict__ bias,
    float* __restrict__ Y, __half* __restrict__ Oh,
    int N, int K)
{
    constexpr int WARPS_M = BMv / 32;            // 4 (BM128) or 2 (BM64)
    constexpr int WARPS_N = 8 / WARPS_M;         // 2 or 4
    constexpr int WNW     = BN / WARPS_N;        // 64 or 32 (warp n-width)
    constexpr int NT      = WNW / 8;             // 8 or 4 n-tiles
    constexpr int NG      = NT / 2;              // 4 or 2 ldmatrix n-groups
    constexpr int A_BYTES = BMv * 128;
    constexpr int STG     = A_BYTES + BN * 128;  // stage bytes (32K / 24K)
    constexpr int A_ITERS = (BMv * 8) / NTHR;    // 4 or 2
    constexpr int B_ITERS = (BN * 8) / NTHR;     // 4

    extern __shared__ __align__(1024) char smem[];
    const uint32_t sb = smem_u32(smem);
    const int tid  = threadIdx.x;
    const int lane = tid & 31;
    const int warp = tid >> 5;
    const int warp_m = (warp % WARPS_M) * 32;
    const int warp_n = (warp / WARPS_M) * WNW;
    const int m0 = blockIdx.y * BMv;
    const int n0 = blockIdx.x * BN;

    const int fr  = lane & 15;
    const int fch = lane >> 4;

    float acc[2][NT][4];
#pragma unroll
    for (int mt = 0; mt < 2; ++mt)
#pragma unroll
        for (int nt = 0; nt < NT; ++nt)
#pragma unroll
            for (int i = 0; i < 4; ++i) acc[mt][nt][i] = 0.f;

    const int ntiles = K >> 6;

    auto prefetch = [&](int s, int kt) {
        const uint32_t stg = sb + s * STG;
        const int kof = kt * 64;
#pragma unroll
        for (int i = 0; i < A_ITERS; ++i) {
            int idx = tid + i * NTHR;
            int r = idx >> 3, ch = idx & 7;
            uint32_t soff = (uint32_t)r * 128 + (uint32_t)((ch ^ (r & 7)) * 16);
            CP_ASYNC16(stg + soff, (const char*)(A + (size_t)(m0 + r) * K + kof + ch * 8));
        }
#pragma unroll
        for (int i = 0; i < B_ITERS; ++i) {
            int idx = tid + i * NTHR;
            int r = idx >> 3, ch = idx & 7;
            uint32_t soff = (uint32_t)r * 128 + (uint32_t)((ch ^ (r & 7)) * 16);
            CP_ASYNC16(stg + A_BYTES + soff,
                       (const char*)(Bw + (size_t)(n0 + r) * K + kof + ch * 8));
        }
    };

    // 2 stages in flight
#pragma unroll
    for (int s = 0; s < 2; ++s) {
        if (s < ntiles) prefetch(s, s);
        CP_COMMIT();
    }

    // precomputed fragment row offsets
    uint32_t ra128[2], ramask[2], rb128[NG], rbmask[NG];
#pragma unroll
    for (int mt = 0; mt < 2; ++mt) {
        int r = warp_m + mt * 16 + fr;
        ra128[mt] = (uint32_t)r * 128;
        ramask[mt] = (uint32_t)(r & 7);
    }
#pragma unroll
    for (int ng = 0; ng < NG; ++ng) {
        int r = warp_n + ng * 16 + fr;
        rb128[ng] = (uint32_t)r * 128;
        rbmask[ng] = (uint32_t)(r & 7);
    }

    int s = 0;
    for (int kt = 0; kt < ntiles; ++kt) {
        const uint32_t abase = sb + s * STG;
        const uint32_t bbase = abase + A_BYTES;

        CP_WAIT1();            // tile kt's group complete (2 in flight)
        __syncthreads();       // all warps done with iter kt-1 -> its slot is refillable

        const int nk = kt + 2;
        int ps = s + 2; if (ps >= SLOTS) ps -= SLOTS;   // == slot of kt-1
        if (nk < ntiles) prefetch(ps, nk);
        CP_COMMIT();

#pragma unroll
        for (int ks = 0; ks < 4; ++ks) {
            const uint32_t chsel = (uint32_t)(ks * 2) + (uint32_t)fch;
            uint32_t af[2][4];
#pragma unroll
            for (int mt = 0; mt < 2; ++mt) {
                uint32_t off = abase + ra128[mt] + ((chsel ^ ramask[mt]) * 16);
                LDSM4(af[mt][0], af[mt][1], af[mt][2], af[mt][3], off);
            }
            uint32_t bf[NG][4];
#pragma unroll
            for (int ng = 0; ng < NG; ++ng) {
                uint32_t off = bbase + rb128[ng] + ((chsel ^ rbmask[ng]) * 16);
                LDSM4(bf[ng][0], bf[ng][1], bf[ng][2], bf[ng][3], off);
            }
#pragma unroll
            for (int mt = 0; mt < 2; ++mt) {
#pragma unroll
                for (int ng = 0; ng < NG; ++ng) {
                    mma16816(acc[mt][ng * 2],     af[mt], bf[ng][0], bf[ng][2]);
                    mma16816(acc[mt][ng * 2 + 1], af[mt], bf[ng][1], bf[ng][3]);
                }
            }
        }
        if (++s >= SLOTS) s = 0;
    }

    // ---- epilogue ----
#pragma unroll
    for (int mt = 0; mt < 2; ++mt) {
#pragma unroll
        for (int nt = 0; nt < NT; ++nt) {
            const int r = m0 + warp_m + mt * 16 + (lane >> 2);
            const int c = n0 + warp_n + nt * 8 + (lane & 3) * 2;
            const float bb0 = __ldg(&bias[c]);
            const float bb1 = __ldg(&bias[c + 1]);
            float v0 = acc[mt][nt][0] + bb0;
            float v1 = acc[mt][nt][1] + bb1;
            float v2 = acc[mt][nt][2] + bb0;
            float v3 = acc[mt][nt][3] + bb1;
            if (RELU) {
                v0 = fmaxf(v0, 0.f); v1 = fmaxf(v1, 0.f);
                v2 = fmaxf(v2, 0.f); v3 = fmaxf(v3, 0.f);
            }
            if (F16_OUT) {
                *reinterpret_cast<__half2*>(Oh + (size_t)r * N + c) =
                    __floats2half2_rn(v0, v1);
                *reinterpret_cast<__half2*>(Oh + (size_t)(r + 8) * N + c) =
                    __floats2half2_rn(v2, v3);
            } else {
                *reinterpret_cast<float2*>(&Y[(size_t)r * N + c]) = make_float2(v0, v1);
                *reinterpret_cast<float2*>(&Y[(size_t)(r + 8) * N + c]) = make_float2(v2, v3);
            }
        }
    }
}

// ---------------- Host launch ----------------
#define SMEM_G1 (SLOTS * (128 * 128 + BN * 128))   // 3 * 32K = 96K  -> 2 CTAs/SM
#define SMEM_G2 (SLOTS * (64 * 128 + BN * 128))    // 3 * 24K = 72K  -> 2 CTAs/SM

extern "C" void kernel_launch(void* const* d_in, const int* in_sizes, int n_in,
                              void* d_out, int out_size) {
    const float* x  = (const float*)d_in[0];
    const float* W1 = (const float*)d_in[1];
    const float* b1 = (const float*)d_in[2];
    const float* W2 = (const float*)d_in[3];
    const float* b2 = (const float*)d_in[4];
    float* y = (float*)d_out;

    __half *xf, *w1, *w2, *hf;
    cudaGetSymbolAddress((void**)&xf, g_xf);
    cudaGetSymbolAddress((void**)&w1, g_w1);
    cudaGetSymbolAddress((void**)&w2, g_w2);
    cudaGetSymbolAddress((void**)&hf, g_hf);

    cudaFuncSetAttribute(gemm_f16<128, true, true>,
                         cudaFuncAttributeMaxDynamicSharedMemorySize, SMEM_G1);
    cudaFuncSetAttribute(gemm_f16<64, false, false>,
                         cudaFuncAttributeMaxDynamicSharedMemorySize, SMEM_G2);

    // Converts
    cvt_f16<<<(B_DIM * N_IN / 8) / 256, 256>>>(x, xf);
    transpose_f16<<<dim3(N_HID / 64, N_IN / 64), 256>>>(W1, w1, N_IN, N_HID);
    transpose_f16<<<dim3(N_OUT / 64, N_HID / 64), 256>>>(W2, w2, N_HID, N_OUT);

    // GEMM1: h = relu(x @ W1 + b1) -> fp16   (grid 32 x 32 = 1024 CTAs)
    gemm_f16<128, true, true><<<dim3(N_HID / BN, B_DIM / 128), NTHR, SMEM_G1>>>(
        xf, w1, b1, nullptr, hf, N_HID, N_IN);

    // GEMM2: y = h @ W2 + b2 (fp32 out)      (grid 8 x 64 = 512 CTAs)
    gemm_f16<64, false, false><<<dim3(N_OUT / BN, B_DIM / 64), NTHR, SMEM_G2>>>(
        hf, w2, b2, y, nullptr, N_OUT, N_HID);
}

// round 9
// speedup vs baseline: 9.6500x; 1.1689x over previous
#include <cuda_runtime.h>
#include <cuda_fp16.h>
#include <stdint.h>

// ---------------- Problem dims ----------------
#define B_DIM  4096
#define N_IN   1024
#define N_HID  4096
#define N_OUT  1024

// ---------------- GEMM tiling ----------------
#define BM 128
#define BN 128
#define BK 64                  // k elems per stage
#define SLOTS 3                // smem slots; 2 in flight
#define NTHR 256
#define A_BYTES (BM * 128)     // 16384  (128 rows x 128B)
#define B_BYTES (BK * 256)     // 16384  (64 k-rows x 256B of n)
#define STG (A_BYTES + B_BYTES)
#define SMEM_G (SLOTS * STG)   // 96K -> 2 CTAs/SM

// ---------------- Device scratch (allocation-free rule) ----------------
__device__ __align__(128) __half g_xf[(size_t)B_DIM * N_IN];
__device__ __align__(128) __half g_w1[(size_t)N_IN * N_HID];    // [K][N] fp16 (no transpose)
__device__ __align__(128) __half g_w2[(size_t)N_HID * N_OUT];   // [K][N] fp16
__device__ __align__(128) __half g_hf[(size_t)B_DIM * N_HID];

// ---------------- PTX helpers ----------------
__device__ __forceinline__ uint32_t smem_u32(const void* p) {
    uint32_t a;
    asm("{ .reg .u64 t; cvta.to.shared.u64 t, %1; cvt.u32.u64 %0, t; }" : "=r"(a) : "l"(p));
    return a;
}
#define CP_ASYNC16(dst, src) \
    asm volatile("cp.async.cg.shared.global [%0], [%1], 16;" :: "r"(dst), "l"(src))
#define CP_COMMIT() asm volatile("cp.async.commit_group;" ::: "memory")
#define CP_WAIT1()  asm volatile("cp.async.wait_group 1;" ::: "memory")

#define LDSM4(r0, r1, r2, r3, a) \
    asm volatile("ldmatrix.sync.aligned.m8n8.x4.shared.b16 {%0,%1,%2,%3}, [%4];" \
                 : "=r"(r0), "=r"(r1), "=r"(r2), "=r"(r3) : "r"(a))
#define LDSM4T(r0, r1, r2, r3, a) \
    asm volatile("ldmatrix.sync.aligned.m8n8.x4.trans.shared.b16 {%0,%1,%2,%3}, [%4];" \
                 : "=r"(r0), "=r"(r1), "=r"(r2), "=r"(r3) : "r"(a))

__device__ __forceinline__ void mma16816(float* d, const uint32_t* a, uint32_t b0, uint32_t b1) {
    asm volatile(
        "mma.sync.aligned.m16n8k16.row.col.f32.f16.f16.f32 "
        "{%0,%1,%2,%3}, {%4,%5,%6,%7}, {%8,%9}, {%0,%1,%2,%3};\n"
        : "+f"(d[0]), "+f"(d[1]), "+f"(d[2]), "+f"(d[3])
        : "r"(a[0]), "r"(a[1]), "r"(a[2]), "r"(a[3]), "r"(b0), "r"(b1));
}

// ---------------- Convert kernel (elementwise fp32 -> fp16) ----------------
__global__ __launch_bounds__(256) void cvt_f16(const float* __restrict__ in,
                                               __half* __restrict__ out) {
    size_t g = (size_t)(blockIdx.x * 256 + threadIdx.x) * 8;
    float4 v0 = *reinterpret_cast<const float4*>(in + g);
    float4 v1 = *reinterpret_cast<const float4*>(in + g + 4);
    float vv[8] = {v0.x, v0.y, v0.z, v0.w, v1.x, v1.y, v1.z, v1.w};
    union { unsigned short us[8]; uint4 q; } p;
#pragma unroll
    for (int j = 0; j < 8; ++j) p.us[j] = __half_as_ushort(__float2half_rn(vv[j]));
    *reinterpret_cast<uint4*>(out + g) = p.q;
}

// ---------------- GEMM: C = act(A @ W + bias) ----------------
// A: [M][K] fp16 row-major (128B k-rows in smem, xor swizzle, normal ldmatrix).
// W: [K][N] fp16 row-major; tiles of 64 k-rows x 256B staged in smem with
//    per-128B xor swizzle; read with ldmatrix.x4.trans -> col-major B frags.
// CTA 128x128, 8 warps (4 M x 2 N), warp tile 32x64; 2 CTAs/SM;
// 3-slot / 2-deep cp.async pipeline, one __syncthreads per k-tile.
template <bool RELU, bool F16_OUT>
__global__ __launch_bounds__(NTHR, 2) void gemm_f16(
    const __half* __restrict__ A, const __half* __restrict__ Bw,
    const float* __restrict__ bias,
    float* __restrict__ Y, __half* __restrict__ Oh,
    int N, int K)
{
    constexpr int NT = 8;     // n-tiles (n8) per warp
    constexpr int NG = 4;     // n16 ldmatrix groups per warp

    extern __shared__ __align__(1024) char smem[];
    const uint32_t sb = smem_u32(smem);
    const int tid  = threadIdx.x;
    const int lane = tid & 31;
    const int warp = tid >> 5;
    const int warp_m = (warp & 3) * 32;    // 4 warps along M
    const int warp_n = (warp >> 2) * 64;   // 2 warps along N
    const int m0 = blockIdx.y * BM;
    const int n0 = blockIdx.x * BN;

    // A-frag lane coords (normal ldmatrix from [M][K])
    const int fr  = lane & 15;
    const int fch = lane >> 4;
    // B-frag lane coords (trans ldmatrix from [K][N])
    const int bj   = lane >> 3;            // matrix index 0..3
    const int bi   = lane & 7;             // row within 8x8
    const int bk0  = (bj & 1) * 8 + bi;    // k-row base within k16 step
    const int cn0  = (warp_n >> 3) + (bj >> 1);  // 16B chunk base within 256B row

    float acc[2][NT][4];
#pragma unroll
    for (int mt = 0; mt < 2; ++mt)
#pragma unroll
        for (int nt = 0; nt < NT; ++nt)
#pragma unroll
            for (int i = 0; i < 4; ++i) acc[mt][nt][i] = 0.f;

    const int ntiles = K >> 6;

    auto prefetch = [&](int s, int kt) {
        const uint32_t stg = sb + s * STG;
        const int kof = kt * 64;
        // A tile: 128 rows x 8 chunks (16B), xor-swizzled in 128B rows
#pragma unroll
        for (int i = 0; i < 4; ++i) {
            int idx = tid + i * NTHR;
            int r = idx >> 3, ch = idx & 7;
            uint32_t soff = (uint32_t)r * 128 + (uint32_t)((ch ^ (r & 7)) * 16);
            CP_ASYNC16(stg + soff, (const char*)(A + (size_t)(m0 + r) * K + kof + ch * 8));
        }
        // B tile: 64 k-rows x 16 chunks (16B) = 256B/row, xor swizzle per 128B half
#pragma unroll
        for (int i = 0; i < 4; ++i) {
            int idx = tid + i * NTHR;
            int r = idx >> 4, c = idx & 15;
            uint32_t soff = A_BYTES + (uint32_t)r * 256 +
                            (uint32_t)(((c & 8) | ((c ^ r) & 7)) * 16);
            CP_ASYNC16(stg + soff,
                       (const char*)(Bw + (size_t)(kof + r) * N + n0 + c * 8));
        }
    };

    // 2 stages in flight
#pragma unroll
    for (int s = 0; s < 2; ++s) {
        if (s < ntiles) prefetch(s, s);
        CP_COMMIT();
    }

    // precomputed A fragment row offsets
    uint32_t ra128[2], ramask[2];
#pragma unroll
    for (int mt = 0; mt < 2; ++mt) {
        int r = warp_m + mt * 16 + fr;
        ra128[mt] = (uint32_t)r * 128;
        ramask[mt] = (uint32_t)(r & 7);
    }

    int s = 0;
    for (int kt = 0; kt < ntiles; ++kt) {
        const uint32_t abase = sb + s * STG;
        const uint32_t bbase = abase + A_BYTES;

        CP_WAIT1();            // tile kt complete (2 in flight)
        __syncthreads();       // all warps done with iter kt-1 -> its slot refillable

        const int nk = kt + 2;
        int ps = s + 2; if (ps >= SLOTS) ps -= SLOTS;   // slot of kt-1
        if (nk < ntiles) prefetch(ps, nk);
        CP_COMMIT();

#pragma unroll
        for (int ks = 0; ks < 4; ++ks) {
            // A fragments (normal ldmatrix)
            const uint32_t chsel = (uint32_t)(ks * 2) + (uint32_t)fch;
            uint32_t af[2][4];
#pragma unroll
            for (int mt = 0; mt < 2; ++mt) {
                uint32_t off = abase + ra128[mt] + ((chsel ^ ramask[mt]) * 16);
                LDSM4(af[mt][0], af[mt][1], af[mt][2], af[mt][3], off);
            }
            // B fragments (trans ldmatrix from k-major tile)
            const uint32_t kr = (uint32_t)(ks * 16 + bk0);
            uint32_t bf[NG][4];
#pragma unroll
            for (int ng = 0; ng < NG; ++ng) {
                uint32_t cn = (uint32_t)(cn0 + ng * 2);
                uint32_t off = bbase + kr * 256 + (((cn & 8) | ((cn ^ kr) & 7)) * 16);
                LDSM4T(bf[ng][0], bf[ng][1], bf[ng][2], bf[ng][3], off);
            }
#pragma unroll
            for (int mt = 0; mt < 2; ++mt) {
#pragma unroll
                for (int ng = 0; ng < NG; ++ng) {
                    // r0,r1 = (k0-7, k8-15) of even n8; r2,r3 = odd n8
                    mma16816(acc[mt][ng * 2],     af[mt], bf[ng][0], bf[ng][1]);
                    mma16816(acc[mt][ng * 2 + 1], af[mt], bf[ng][2], bf[ng][3]);
                }
            }
        }
        if (++s >= SLOTS) s = 0;
    }

    // ---- epilogue ----
#pragma unroll
    for (int mt = 0; mt < 2; ++mt) {
#pragma unroll
        for (int nt = 0; nt < NT; ++nt) {
            const int r = m0 + warp_m + mt * 16 + (lane >> 2);
            const int c = n0 + warp_n + nt * 8 + (lane & 3) * 2;
            const float bb0 = __ldg(&bias[c]);
            const float bb1 = __ldg(&bias[c + 1]);
            float v0 = acc[mt][nt][0] + bb0;
            float v1 = acc[mt][nt][1] + bb1;
            float v2 = acc[mt][nt][2] + bb0;
            float v3 = acc[mt][nt][3] + bb1;
            if (RELU) {
                v0 = fmaxf(v0, 0.f); v1 = fmaxf(v1, 0.f);
                v2 = fmaxf(v2, 0.f); v3 = fmaxf(v3, 0.f);
            }
            if (F16_OUT) {
                *reinterpret_cast<__half2*>(Oh + (size_t)r * N + c) =
                    __floats2half2_rn(v0, v1);
                *reinterpret_cast<__half2*>(Oh + (size_t)(r + 8) * N + c) =
                    __floats2half2_rn(v2, v3);
            } else {
                *reinterpret_cast<float2*>(&Y[(size_t)r * N + c]) = make_float2(v0, v1);
                *reinterpret_cast<float2*>(&Y[(size_t)(r + 8) * N + c]) = make_float2(v2, v3);
            }
        }
    }
}

// ---------------- Host launch ----------------
extern "C" void kernel_launch(void* const* d_in, const int* in_sizes, int n_in,
                              void* d_out, int out_size) {
    const float* x  = (const float*)d_in[0];
    const float* W1 = (const float*)d_in[1];
    const float* b1 = (const float*)d_in[2];
    const float* W2 = (const float*)d_in[3];
    const float* b2 = (const float*)d_in[4];
    float* y = (float*)d_out;

    __half *xf, *w1, *w2, *hf;
    cudaGetSymbolAddress((void**)&xf, g_xf);
    cudaGetSymbolAddress((void**)&w1, g_w1);
    cudaGetSymbolAddress((void**)&w2, g_w2);
    cudaGetSymbolAddress((void**)&hf, g_hf);

    cudaFuncSetAttribute(gemm_f16<true, true>,
                         cudaFuncAttributeMaxDynamicSharedMemorySize, SMEM_G);
    cudaFuncSetAttribute(gemm_f16<false, false>,
                         cudaFuncAttributeMaxDynamicSharedMemorySize, SMEM_G);

    // Elementwise converts only (no transposes; GEMM consumes [K][N] directly)
    cvt_f16<<<(B_DIM * N_IN / 8) / 256, 256>>>(x, xf);
    cvt_f16<<<((size_t)N_IN * N_HID / 8) / 256, 256>>>(W1, w1);
    cvt_f16<<<((size_t)N_HID * N_OUT / 8) / 256, 256>>>(W2, w2);

    // GEMM1: h = relu(x @ W1 + b1) -> fp16   (grid 32 x 32 = 1024 CTAs)
    gemm_f16<true, true><<<dim3(N_HID / BN, B_DIM / BM), NTHR, SMEM_G>>>(
        xf, w1, b1, nullptr, hf, N_HID, N_IN);

    // GEMM2: y = h @ W2 + b2 (fp32 out)      (grid 8 x 32 = 256 CTAs, single wave)
    gemm_f16<false, false><<<dim3(N_OUT / BN, B_DIM / BM), NTHR, SMEM_G>>>(
        hf, w2, b2, y, nullptr, N_OUT, N_HID);
}